// round 15
// baseline (speedup 1.0000x reference)
#include <cuda_runtime.h>
#include <cuda_bf16.h>
#include <math.h>

// Problem constants
#define BB   64
#define CC   2048
#define HW   196
#define MM   32
#define NC   396
#define KTOT (MM * CC)          // 65536

// kernel-1 (tf32 tensor): K-split 4 x N-split 2
#define KS1   4
#define KSL1  (CC / KS1)        // 512
#define NS1   2                 // hw split
#define NW1   112               // hw columns per block
#define XST   136               // xs row stride (words); 136%32=8 -> conflict-free
#define WST   36                // Wa row stride

// kernel-2 (tf32 + cp.async staging) — frozen R13
#define K2ST  200               // smem row stride; 200%32=8

// kernel-3: tf32 + cp.async, 4-stage pipeline, 128 thr, KS3=64
#define KS3       64
#define KSLICE3   (KTOT / KS3)  // 1024
#define KCH       32
#define NCH       (KSLICE3 / KCH)  // 32
#define NT3       7
#define SROW      36
#define ST3       4             // pipeline stages

// -------- scratch (device globals; no runtime allocation) --------
__device__ float    g_part1[KS1 * BB * MM * HW];  // [ks][b][m][hw]
__device__ float    g_A    [BB * MM * HW];        // [b][m][hw]
__device__ unsigned g_bap  [BB * KTOT];           // tf32 bits, [b][m*2048+c]
__device__ float    g_part3[KS3 * BB * NC];       // [ks][b][n] 6.5 MB

// -------- tf32 helpers (validated R7/R8) --------
__device__ __forceinline__ unsigned f2tf(float f) {
    unsigned r;
    asm("cvt.rna.tf32.f32 %0, %1;" : "=r"(r) : "f"(f));
    return r;
}
__device__ __forceinline__ unsigned u2tf(unsigned u) {
    return f2tf(__uint_as_float(u));
}
__device__ __forceinline__ void mma_tf32(float* d,
                                         unsigned a0, unsigned a1,
                                         unsigned a2, unsigned a3,
                                         unsigned b0, unsigned b1) {
    asm("mma.sync.aligned.m16n8k8.row.col.f32.tf32.tf32.f32 "
        "{%0,%1,%2,%3}, {%4,%5,%6,%7}, {%8,%9}, {%0,%1,%2,%3};"
        : "+f"(d[0]), "+f"(d[1]), "+f"(d[2]), "+f"(d[3])
        : "r"(a0), "r"(a1), "r"(a2), "r"(a3), "r"(b0), "r"(b1));
}
// -------- cp.async helpers --------
__device__ __forceinline__ void cp16(unsigned dst_smem, const void* src) {
    asm volatile("cp.async.cg.shared.global [%0], [%1], 16;"
                 :: "r"(dst_smem), "l"(src));
}
__device__ __forceinline__ void cp16z(unsigned dst_smem, const void* src, int srcbytes) {
    asm volatile("cp.async.cg.shared.global [%0], [%1], 16, %2;"
                 :: "r"(dst_smem), "l"(src), "r"(srcbytes));
}
__device__ __forceinline__ void cp_commit() {
    asm volatile("cp.async.commit_group;");
}

// ============================================================================
// Kernel 1 (tf32, N-split): partial logits. grid (64 b, 4 ks, 2 nb) = 512
// blocks, block 256 (8 warps: 2m x 4n, warp tile 16m x 32n, block 32m x 128n
// covering 112 real hw columns + zero pad). Double-buffered, reg-prefetched.
// smem 44 KB -> deep residency; traffic identical to the 256-block version.
// ============================================================================
__global__ __launch_bounds__(256) void k1_logits(const float* __restrict__ x,
                                                 const float* __restrict__ Wa) {
    extern __shared__ unsigned sm1[];
    unsigned* xs  = sm1;                 // [2][32*XST]
    unsigned* was = sm1 + 2 * 32 * XST;  // [2][32*WST]

    const int b  = blockIdx.x;
    const int ks = blockIdx.y;
    const int nb = blockIdx.z;
    const int hwb = nb * NW1;
    const int t  = threadIdx.x;
    const int w    = t >> 5;
    const int lane = t & 31;
    const int g    = lane >> 2;
    const int q    = lane & 3;
    const int m0   = (w & 1) * 16;
    const int n0w  = (w >> 1) * 32;

    // zero pad columns 112..135 of both x buffers once (never re-written)
    for (int i = t; i < 2 * 32 * 24; i += 256) {
        const int buf = i / (32 * 24);
        const int r   = (i % (32 * 24)) / 24;
        const int c   = (i % (32 * 24)) % 24;
        xs[buf * (32 * XST) + r * XST + NW1 + c] = 0;
    }

    float d[4][4];
#pragma unroll
    for (int j = 0; j < 4; ++j)
#pragma unroll
        for (int r = 0; r < 4; ++r) d[j][r] = 0.0f;

    const float* xb = x + (size_t)b * CC * HW;
    const int c_base = ks * KSL1;

    const int wrow = t >> 3, wcol4 = t & 7;   // Wa staging: 1 float4/thread

    // x staging: 32 rows x 28 float4 = 896 items over 256 threads (r<4)
    float4 xv[4], wv;
#pragma unroll
    for (int r = 0; r < 4; ++r) {
        const int idx = t + 256 * r;
        if (idx < 896) {
            const int row = idx / 28, col4 = idx % 28;
            const int gc4 = 28 * nb + col4;
            xv[r] = (gc4 < 49)
                ? *(const float4*)(xb + (size_t)(c_base + row) * HW + 4 * gc4)
                : make_float4(0.f, 0.f, 0.f, 0.f);
        }
    }
    wv = *(const float4*)(Wa + (size_t)wrow * CC + c_base + 4 * wcol4);

    for (int ch = 0; ch < KSL1 / 32; ++ch) {
        const int buf = ch & 1;
        unsigned* xsb = xs  + buf * (32 * XST);
        unsigned* wsb = was + buf * (32 * WST);
#pragma unroll
        for (int r = 0; r < 4; ++r) {
            const int idx = t + 256 * r;
            if (idx < 896) {
                const int row = idx / 28, col4 = idx % 28;
                unsigned* dst = &xsb[row * XST + 4 * col4];
                dst[0] = f2tf(xv[r].x); dst[1] = f2tf(xv[r].y);
                dst[2] = f2tf(xv[r].z); dst[3] = f2tf(xv[r].w);
            }
        }
        {
            unsigned* dst = &wsb[wrow * WST + 4 * wcol4];
            dst[0] = f2tf(wv.x); dst[1] = f2tf(wv.y);
            dst[2] = f2tf(wv.z); dst[3] = f2tf(wv.w);
        }
        __syncthreads();

        if (ch + 1 < KSL1 / 32) {
            const int cb = c_base + (ch + 1) * 32;
#pragma unroll
            for (int r = 0; r < 4; ++r) {
                const int idx = t + 256 * r;
                if (idx < 896) {
                    const int row = idx / 28, col4 = idx % 28;
                    const int gc4 = 28 * nb + col4;
                    xv[r] = (gc4 < 49)
                        ? *(const float4*)(xb + (size_t)(cb + row) * HW + 4 * gc4)
                        : make_float4(0.f, 0.f, 0.f, 0.f);
                }
            }
            wv = *(const float4*)(Wa + (size_t)wrow * CC + cb + 4 * wcol4);
        }

#pragma unroll
        for (int s = 0; s < 4; ++s) {
            const int k0 = 8 * s;
            const unsigned a0 = wsb[(m0 + g)     * WST + k0 + q];
            const unsigned a1 = wsb[(m0 + 8 + g) * WST + k0 + q];
            const unsigned a2 = wsb[(m0 + g)     * WST + k0 + q + 4];
            const unsigned a3 = wsb[(m0 + 8 + g) * WST + k0 + q + 4];
#pragma unroll
            for (int j = 0; j < 4; ++j) {
                const int n = n0w + 8 * j + g;
                const unsigned b0 = xsb[(k0 + q)     * XST + n];
                const unsigned b1 = xsb[(k0 + q + 4) * XST + n];
                mma_tf32(d[j], a0, a1, a2, a3, b0, b1);
            }
        }
        __syncthreads();
    }

    const size_t base = ((size_t)ks * BB + b) * (MM * HW);
#pragma unroll
    for (int j = 0; j < 4; ++j) {
        const int nl = n0w + 8 * j + 2 * q;          // local col (pair start)
        if (nl < NW1 && hwb + nl < 196) {            // own range, in bounds
            const int hw = hwb + nl;
            float* p0 = g_part1 + base + (size_t)(m0 + g) * HW + hw;
            p0[0] = d[j][0]; p0[1] = d[j][1];
            float* p1 = g_part1 + base + (size_t)(m0 + 8 + g) * HW + hw;
            p1[0] = d[j][2]; p1[1] = d[j][3];
        }
    }
}

// ============================================================================
// Kernel 1b: reduce KS1 split-K partials, add bias, sigmoid -> g_A.
// ============================================================================
__global__ __launch_bounds__(256) void k1b_sigmoid(const float* __restrict__ ba) {
    const int i = blockIdx.x * 256 + threadIdx.x;
    const int m = (i / HW) & (MM - 1);
    float z = ba[m];
#pragma unroll
    for (int s = 0; s < KS1; ++s)
        z += g_part1[(size_t)s * (BB * MM * HW) + i];
    g_A[i] = 1.0f / (1.0f + expf(-z));
}

// ============================================================================
// Kernel 2 (tf32 + cp.async staging, frozen R13): bap -> tf32 bits in g_bap.
// ============================================================================
__global__ __launch_bounds__(128) void k2_bap(const float* __restrict__ x) {
    extern __shared__ unsigned sm2u[];
    unsigned* as = sm2u;             // [32][200] fp32 bits
    unsigned* xs = sm2u + 32 * K2ST; // [64][200] fp32 bits

    const int b  = blockIdx.y;
    const int c0 = blockIdx.x * 64;
    const int t  = threadIdx.x;
    const int w    = t >> 5;
    const int lane = t & 31;
    const int g    = lane >> 2;
    const int q    = lane & 3;
    const int n0w  = w * 16;

    const unsigned abase = (unsigned)__cvta_generic_to_shared(as);
    const unsigned xbase = (unsigned)__cvta_generic_to_shared(xs);

    {
        const float* asrc = g_A + (size_t)b * (MM * HW);
        for (int i = t; i < 32 * 49; i += 128) {
            const int row = i / 49, col4 = i % 49;
            cp16(abase + (row * K2ST + 4 * col4) * 4,
                 asrc + (size_t)row * HW + 4 * col4);
        }
        const float* xsrc = x + ((size_t)b * CC + c0) * HW;
        for (int i = t; i < 64 * 49; i += 128) {
            const int row = i / 49, col4 = i % 49;
            cp16(xbase + (row * K2ST + 4 * col4) * 4,
                 xsrc + (size_t)row * HW + 4 * col4);
        }
        cp_commit();
    }
    if (t < 32 * 4) as[(t >> 2) * K2ST + 196 + (t & 3)] = 0;
    for (int i = t; i < 64 * 4; i += 128)
        xs[(i >> 2) * K2ST + 196 + (i & 3)] = 0;

    asm volatile("cp.async.wait_group 0;");
    __syncthreads();

    float d[2][2][4];
#pragma unroll
    for (int mi = 0; mi < 2; ++mi)
#pragma unroll
        for (int nj = 0; nj < 2; ++nj)
#pragma unroll
            for (int r = 0; r < 4; ++r) d[mi][nj][r] = 0.0f;

#pragma unroll
    for (int s = 0; s < 25; ++s) {
        const int k0 = 8 * s;
        unsigned b0[2], b1[2];
#pragma unroll
        for (int nj = 0; nj < 2; ++nj) {
            const int n = n0w + 8 * nj + g;
            b0[nj] = u2tf(xs[n * K2ST + k0 + q]);
            b1[nj] = u2tf(xs[n * K2ST + k0 + q + 4]);
        }
#pragma unroll
        for (int mi = 0; mi < 2; ++mi) {
            const unsigned a0 = u2tf(as[(16 * mi + g)     * K2ST + k0 + q]);
            const unsigned a1 = u2tf(as[(16 * mi + 8 + g) * K2ST + k0 + q]);
            const unsigned a2 = u2tf(as[(16 * mi + g)     * K2ST + k0 + q + 4]);
            const unsigned a3 = u2tf(as[(16 * mi + 8 + g) * K2ST + k0 + q + 4]);
#pragma unroll
            for (int nj = 0; nj < 2; ++nj)
                mma_tf32(d[mi][nj], a0, a1, a2, a3, b0[nj], b1[nj]);
        }
    }

    const float inv = 1.0f / 196.0f;
#pragma unroll
    for (int mi = 0; mi < 2; ++mi) {
#pragma unroll
        for (int nj = 0; nj < 2; ++nj) {
            const int c = c0 + n0w + 8 * nj + 2 * q;
            const int m = 16 * mi + g;
            unsigned* p0 = g_bap + (size_t)b * KTOT + (size_t)m * CC + c;
            p0[0] = f2tf(d[mi][nj][0] * inv);
            p0[1] = f2tf(d[mi][nj][1] * inv);
            unsigned* p1 = g_bap + (size_t)b * KTOT + (size_t)(m + 8) * CC + c;
            p1[0] = f2tf(d[mi][nj][2] * inv);
            p1[1] = f2tf(d[mi][nj][3] * inv);
        }
    }
}

// ============================================================================
// Kernel 3 (tf32 + cp.async, 4-stage, KS3=64): partials bap @ Wc^T.
// grid (64, 7), block 128 (4 warps, 16n each). Issue distance 3; exact
// drain waits. KS3=64 halves g_part3 traffic vs R14 (k3 itself measured
// insensitive to KS3).
// ============================================================================
__global__ __launch_bounds__(128, 4) void k3_gemm(const float* __restrict__ Wc) {
    extern __shared__ unsigned sm3[];
    unsigned* bs  = sm3;                       // [ST3][64*SROW] tf32 bits
    unsigned* wsm = sm3 + ST3 * 64 * SROW;     // [ST3][64*SROW] fp32 bits

    const int ks = blockIdx.x;
    const int n0 = blockIdx.y * 64;
    const int t  = threadIdx.x;
    const int w    = t >> 5;
    const int lane = t & 31;
    const int g    = lane >> 2;
    const int q    = lane & 3;

    const size_t kbase = (size_t)ks * KSLICE3;

    int srow[4], sk4[4];
#pragma unroll
    for (int r = 0; r < 4; ++r) {
        const int idx = t + 128 * r;
        srow[r] = idx >> 3;
        sk4[r]  = idx & 7;
    }
    unsigned bdst[4], wdst[4];
#pragma unroll
    for (int r = 0; r < 4; ++r) {
        bdst[r] = (unsigned)__cvta_generic_to_shared(&bs[srow[r] * SROW + 4 * sk4[r]]);
        wdst[r] = (unsigned)__cvta_generic_to_shared(&wsm[srow[r] * SROW + 4 * sk4[r]]);
    }
    const unsigned stage_bytes = 64 * SROW * 4;

    float d[4][2][4];
#pragma unroll
    for (int i = 0; i < 4; ++i)
#pragma unroll
        for (int j = 0; j < 2; ++j)
#pragma unroll
            for (int r = 0; r < 4; ++r) d[i][j][r] = 0.0f;

    auto issue = [&](int ch) {
        const int st = ch % ST3;
        const size_t kb = kbase + (size_t)ch * KCH;
#pragma unroll
        for (int r = 0; r < 4; ++r) {
            cp16(bdst[r] + st * stage_bytes,
                 g_bap + (size_t)srow[r] * KTOT + kb + 4 * sk4[r]);
            const int n = n0 + srow[r];
            const float* src = (n < NC)
                ? Wc + (size_t)n * KTOT + kb + 4 * sk4[r] : Wc;
            cp16z(wdst[r] + st * stage_bytes, src, (n < NC) ? 16 : 0);
        }
        cp_commit();
    };

    issue(0);
    issue(1);
    issue(2);

    for (int ch = 0; ch < NCH; ++ch) {
        if (ch + 3 < NCH) {
            issue(ch + 3);
            asm volatile("cp.async.wait_group 3;");
        } else if (ch + 2 < NCH) {
            asm volatile("cp.async.wait_group 2;");
        } else if (ch + 1 < NCH) {
            asm volatile("cp.async.wait_group 1;");
        } else {
            asm volatile("cp.async.wait_group 0;");
        }
        __syncthreads();

        const int st = ch % ST3;
        const unsigned* bsb = bs  + st * (64 * SROW);
        const unsigned* wsb = wsm + st * (64 * SROW);
#pragma unroll
        for (int s = 0; s < 4; ++s) {
            const int k0 = 8 * s;
            unsigned b0[2], b1[2];
#pragma unroll
            for (int j = 0; j < 2; ++j) {
                const int n = 16 * w + 8 * j + g;
                b0[j] = u2tf(wsb[n * SROW + k0 + q]);
                b1[j] = u2tf(wsb[n * SROW + k0 + q + 4]);
            }
#pragma unroll
            for (int i = 0; i < 4; ++i) {
                const unsigned a0 = bsb[(16 * i + g)     * SROW + k0 + q];
                const unsigned a1 = bsb[(16 * i + 8 + g) * SROW + k0 + q];
                const unsigned a2 = bsb[(16 * i + g)     * SROW + k0 + q + 4];
                const unsigned a3 = bsb[(16 * i + 8 + g) * SROW + k0 + q + 4];
#pragma unroll
                for (int j = 0; j < 2; ++j)
                    mma_tf32(d[i][j], a0, a1, a2, a3, b0[j], b1[j]);
            }
        }
        __syncthreads();
    }

#pragma unroll
    for (int i = 0; i < 4; ++i) {
#pragma unroll
        for (int j = 0; j < 2; ++j) {
            const int n = n0 + 16 * w + 8 * j + 2 * q;
            if (n < NC) {
                const int m0 = 16 * i + g;
                float* p0 = g_part3 + ((size_t)ks * BB + m0) * NC + n;
                p0[0] = d[i][j][0];
                p0[1] = d[i][j][1];
                float* p1 = g_part3 + ((size_t)ks * BB + m0 + 8) * NC + n;
                p1[0] = d[i][j][2];
                p1[1] = d[i][j][3];
            }
        }
    }
}

// ============================================================================
// Kernel 3b: reduce K-split partials + bias -> out [64][396].
// ============================================================================
__global__ __launch_bounds__(256) void k3_reduce(const float* __restrict__ bc,
                                                 float* __restrict__ out) {
    const int i = blockIdx.x * 256 + threadIdx.x;
    const int n = i % NC;
    float s = bc[n];
#pragma unroll 16
    for (int j = 0; j < KS3; ++j)
        s += g_part3[(size_t)j * (BB * NC) + i];
    out[i] = s;
}

// ============================================================================
extern "C" void kernel_launch(void* const* d_in, const int* in_sizes, int n_in,
                              void* d_out, int out_size) {
    const float* x  = (const float*)d_in[0];
    const float* Wa = (const float*)d_in[1];
    const float* ba = (const float*)d_in[2];
    const float* Wc = (const float*)d_in[3];
    const float* bc = (const float*)d_in[4];
    float* out = (float*)d_out;

    const int smem_k1 = (2 * 32 * XST + 2 * 32 * WST) * 4;   // 44032 B
    const int smem_k2 = (32 + 64) * K2ST * 4;                // 76800 B
    const int smem_k3 = 2 * ST3 * 64 * SROW * 4;             // 73728 B
    cudaFuncSetAttribute(k1_logits, cudaFuncAttributeMaxDynamicSharedMemorySize, smem_k1);
    cudaFuncSetAttribute(k2_bap,    cudaFuncAttributeMaxDynamicSharedMemorySize, smem_k2);
    cudaFuncSetAttribute(k3_gemm,   cudaFuncAttributeMaxDynamicSharedMemorySize, smem_k3);

    k1_logits<<<dim3(BB, KS1, NS1), 256, smem_k1>>>(x, Wa);
    k1b_sigmoid<<<(BB * MM * HW) / 256, 256>>>(ba);
    k2_bap<<<dim3(CC / 64, BB), 128, smem_k2>>>(x);
    k3_gemm<<<dim3(KS3, NT3), 128, smem_k3>>>(Wc);
    k3_reduce<<<(BB * NC) / 256, 256>>>(bc, out);

    (void)in_sizes; (void)n_in; (void)out_size;
}

// round 16
// speedup vs baseline: 1.0003x; 1.0003x over previous
#include <cuda_runtime.h>
#include <cuda_bf16.h>
#include <math.h>

// Problem constants
#define BB   64
#define CC   2048
#define HW   196
#define MM   32
#define NC   396
#define KTOT (MM * CC)          // 65536

// kernel-1 (tf32 tensor): K-split 4 x N-split 2
#define KS1   4
#define KSL1  (CC / KS1)        // 512
#define NS1   2                 // hw split
#define NW1   112               // hw columns per block
#define XST   136               // xs row stride (words); 136%32=8 -> conflict-free
#define WST   36                // Wa row stride

// kernel-2 (tf32 + cp.async staging) — frozen R13
#define K2ST  200               // smem row stride; 200%32=8

// kernel-3: tf32 + cp.async, 4-stage pipeline, 128 thr, KS3=64
#define KS3       64
#define KSLICE3   (KTOT / KS3)  // 1024
#define KCH       32
#define NCH       (KSLICE3 / KCH)  // 32
#define NT3       7
#define SROW      36
#define ST3       4             // pipeline stages

// -------- scratch (device globals; no runtime allocation) --------
__device__ float    g_part1[KS1 * BB * MM * HW];  // [ks][b][m][hw]
__device__ float    g_A    [BB * MM * HW];        // [b][m][hw]
__device__ unsigned g_bap  [BB * KTOT];           // tf32 bits, [b][m*2048+c]
__device__ float    g_part3[KS3 * BB * NC];       // [ks][b][n] 6.5 MB

// -------- tf32 helpers (validated R7/R8) --------
__device__ __forceinline__ unsigned f2tf(float f) {
    unsigned r;
    asm("cvt.rna.tf32.f32 %0, %1;" : "=r"(r) : "f"(f));
    return r;
}
__device__ __forceinline__ unsigned u2tf(unsigned u) {
    return f2tf(__uint_as_float(u));
}
__device__ __forceinline__ void mma_tf32(float* d,
                                         unsigned a0, unsigned a1,
                                         unsigned a2, unsigned a3,
                                         unsigned b0, unsigned b1) {
    asm("mma.sync.aligned.m16n8k8.row.col.f32.tf32.tf32.f32 "
        "{%0,%1,%2,%3}, {%4,%5,%6,%7}, {%8,%9}, {%0,%1,%2,%3};"
        : "+f"(d[0]), "+f"(d[1]), "+f"(d[2]), "+f"(d[3])
        : "r"(a0), "r"(a1), "r"(a2), "r"(a3), "r"(b0), "r"(b1));
}
// -------- cp.async helpers --------
__device__ __forceinline__ void cp16(unsigned dst_smem, const void* src) {
    asm volatile("cp.async.cg.shared.global [%0], [%1], 16;"
                 :: "r"(dst_smem), "l"(src));
}
__device__ __forceinline__ void cp16z(unsigned dst_smem, const void* src, int srcbytes) {
    asm volatile("cp.async.cg.shared.global [%0], [%1], 16, %2;"
                 :: "r"(dst_smem), "l"(src), "r"(srcbytes));
}
__device__ __forceinline__ void cp_commit() {
    asm volatile("cp.async.commit_group;");
}

// ============================================================================
// Kernel 1 (tf32, N-split): partial logits. grid (64 b, 4 ks, 2 nb) = 512
// blocks, block 256 (8 warps: 2m x 4n, warp tile 16m x 32n, block 32m x 128n
// covering 112 real hw columns + zero pad). Double-buffered, reg-prefetched.
// smem 44 KB -> deep residency; traffic identical to the 256-block version.
// ============================================================================
__global__ __launch_bounds__(256) void k1_logits(const float* __restrict__ x,
                                                 const float* __restrict__ Wa) {
    extern __shared__ unsigned sm1[];
    unsigned* xs  = sm1;                 // [2][32*XST]
    unsigned* was = sm1 + 2 * 32 * XST;  // [2][32*WST]

    const int b  = blockIdx.x;
    const int ks = blockIdx.y;
    const int nb = blockIdx.z;
    const int hwb = nb * NW1;
    const int t  = threadIdx.x;
    const int w    = t >> 5;
    const int lane = t & 31;
    const int g    = lane >> 2;
    const int q    = lane & 3;
    const int m0   = (w & 1) * 16;
    const int n0w  = (w >> 1) * 32;

    // zero pad columns 112..135 of both x buffers once (never re-written)
    for (int i = t; i < 2 * 32 * 24; i += 256) {
        const int buf = i / (32 * 24);
        const int r   = (i % (32 * 24)) / 24;
        const int c   = (i % (32 * 24)) % 24;
        xs[buf * (32 * XST) + r * XST + NW1 + c] = 0;
    }

    float d[4][4];
#pragma unroll
    for (int j = 0; j < 4; ++j)
#pragma unroll
        for (int r = 0; r < 4; ++r) d[j][r] = 0.0f;

    const float* xb = x + (size_t)b * CC * HW;
    const int c_base = ks * KSL1;

    const int wrow = t >> 3, wcol4 = t & 7;   // Wa staging: 1 float4/thread

    // x staging: 32 rows x 28 float4 = 896 items over 256 threads (r<4)
    float4 xv[4], wv;
#pragma unroll
    for (int r = 0; r < 4; ++r) {
        const int idx = t + 256 * r;
        if (idx < 896) {
            const int row = idx / 28, col4 = idx % 28;
            const int gc4 = 28 * nb + col4;
            xv[r] = (gc4 < 49)
                ? *(const float4*)(xb + (size_t)(c_base + row) * HW + 4 * gc4)
                : make_float4(0.f, 0.f, 0.f, 0.f);
        }
    }
    wv = *(const float4*)(Wa + (size_t)wrow * CC + c_base + 4 * wcol4);

    for (int ch = 0; ch < KSL1 / 32; ++ch) {
        const int buf = ch & 1;
        unsigned* xsb = xs  + buf * (32 * XST);
        unsigned* wsb = was + buf * (32 * WST);
#pragma unroll
        for (int r = 0; r < 4; ++r) {
            const int idx = t + 256 * r;
            if (idx < 896) {
                const int row = idx / 28, col4 = idx % 28;
                unsigned* dst = &xsb[row * XST + 4 * col4];
                dst[0] = f2tf(xv[r].x); dst[1] = f2tf(xv[r].y);
                dst[2] = f2tf(xv[r].z); dst[3] = f2tf(xv[r].w);
            }
        }
        {
            unsigned* dst = &wsb[wrow * WST + 4 * wcol4];
            dst[0] = f2tf(wv.x); dst[1] = f2tf(wv.y);
            dst[2] = f2tf(wv.z); dst[3] = f2tf(wv.w);
        }
        __syncthreads();

        if (ch + 1 < KSL1 / 32) {
            const int cb = c_base + (ch + 1) * 32;
#pragma unroll
            for (int r = 0; r < 4; ++r) {
                const int idx = t + 256 * r;
                if (idx < 896) {
                    const int row = idx / 28, col4 = idx % 28;
                    const int gc4 = 28 * nb + col4;
                    xv[r] = (gc4 < 49)
                        ? *(const float4*)(xb + (size_t)(cb + row) * HW + 4 * gc4)
                        : make_float4(0.f, 0.f, 0.f, 0.f);
                }
            }
            wv = *(const float4*)(Wa + (size_t)wrow * CC + cb + 4 * wcol4);
        }

#pragma unroll
        for (int s = 0; s < 4; ++s) {
            const int k0 = 8 * s;
            const unsigned a0 = wsb[(m0 + g)     * WST + k0 + q];
            const unsigned a1 = wsb[(m0 + 8 + g) * WST + k0 + q];
            const unsigned a2 = wsb[(m0 + g)     * WST + k0 + q + 4];
            const unsigned a3 = wsb[(m0 + 8 + g) * WST + k0 + q + 4];
#pragma unroll
            for (int j = 0; j < 4; ++j) {
                const int n = n0w + 8 * j + g;
                const unsigned b0 = xsb[(k0 + q)     * XST + n];
                const unsigned b1 = xsb[(k0 + q + 4) * XST + n];
                mma_tf32(d[j], a0, a1, a2, a3, b0, b1);
            }
        }
        __syncthreads();
    }

    const size_t base = ((size_t)ks * BB + b) * (MM * HW);
#pragma unroll
    for (int j = 0; j < 4; ++j) {
        const int nl = n0w + 8 * j + 2 * q;          // local col (pair start)
        if (nl < NW1 && hwb + nl < 196) {            // own range, in bounds
            const int hw = hwb + nl;
            float* p0 = g_part1 + base + (size_t)(m0 + g) * HW + hw;
            p0[0] = d[j][0]; p0[1] = d[j][1];
            float* p1 = g_part1 + base + (size_t)(m0 + 8 + g) * HW + hw;
            p1[0] = d[j][2]; p1[1] = d[j][3];
        }
    }
}

// ============================================================================
// Kernel 1b: reduce KS1 split-K partials, add bias, sigmoid -> g_A.
// ============================================================================
__global__ __launch_bounds__(256) void k1b_sigmoid(const float* __restrict__ ba) {
    const int i = blockIdx.x * 256 + threadIdx.x;
    const int m = (i / HW) & (MM - 1);
    float z = ba[m];
#pragma unroll
    for (int s = 0; s < KS1; ++s)
        z += g_part1[(size_t)s * (BB * MM * HW) + i];
    g_A[i] = 1.0f / (1.0f + expf(-z));
}

// ============================================================================
// Kernel 2 (tf32 + cp.async staging, frozen R13): bap -> tf32 bits in g_bap.
// ============================================================================
__global__ __launch_bounds__(128) void k2_bap(const float* __restrict__ x) {
    extern __shared__ unsigned sm2u[];
    unsigned* as = sm2u;             // [32][200] fp32 bits
    unsigned* xs = sm2u + 32 * K2ST; // [64][200] fp32 bits

    const int b  = blockIdx.y;
    const int c0 = blockIdx.x * 64;
    const int t  = threadIdx.x;
    const int w    = t >> 5;
    const int lane = t & 31;
    const int g    = lane >> 2;
    const int q    = lane & 3;
    const int n0w  = w * 16;

    const unsigned abase = (unsigned)__cvta_generic_to_shared(as);
    const unsigned xbase = (unsigned)__cvta_generic_to_shared(xs);

    {
        const float* asrc = g_A + (size_t)b * (MM * HW);
        for (int i = t; i < 32 * 49; i += 128) {
            const int row = i / 49, col4 = i % 49;
            cp16(abase + (row * K2ST + 4 * col4) * 4,
                 asrc + (size_t)row * HW + 4 * col4);
        }
        const float* xsrc = x + ((size_t)b * CC + c0) * HW;
        for (int i = t; i < 64 * 49; i += 128) {
            const int row = i / 49, col4 = i % 49;
            cp16(xbase + (row * K2ST + 4 * col4) * 4,
                 xsrc + (size_t)row * HW + 4 * col4);
        }
        cp_commit();
    }
    if (t < 32 * 4) as[(t >> 2) * K2ST + 196 + (t & 3)] = 0;
    for (int i = t; i < 64 * 4; i += 128)
        xs[(i >> 2) * K2ST + 196 + (i & 3)] = 0;

    asm volatile("cp.async.wait_group 0;");
    __syncthreads();

    float d[2][2][4];
#pragma unroll
    for (int mi = 0; mi < 2; ++mi)
#pragma unroll
        for (int nj = 0; nj < 2; ++nj)
#pragma unroll
            for (int r = 0; r < 4; ++r) d[mi][nj][r] = 0.0f;

#pragma unroll
    for (int s = 0; s < 25; ++s) {
        const int k0 = 8 * s;
        unsigned b0[2], b1[2];
#pragma unroll
        for (int nj = 0; nj < 2; ++nj) {
            const int n = n0w + 8 * nj + g;
            b0[nj] = u2tf(xs[n * K2ST + k0 + q]);
            b1[nj] = u2tf(xs[n * K2ST + k0 + q + 4]);
        }
#pragma unroll
        for (int mi = 0; mi < 2; ++mi) {
            const unsigned a0 = u2tf(as[(16 * mi + g)     * K2ST + k0 + q]);
            const unsigned a1 = u2tf(as[(16 * mi + 8 + g) * K2ST + k0 + q]);
            const unsigned a2 = u2tf(as[(16 * mi + g)     * K2ST + k0 + q + 4]);
            const unsigned a3 = u2tf(as[(16 * mi + 8 + g) * K2ST + k0 + q + 4]);
#pragma unroll
            for (int nj = 0; nj < 2; ++nj)
                mma_tf32(d[mi][nj], a0, a1, a2, a3, b0[nj], b1[nj]);
        }
    }

    const float inv = 1.0f / 196.0f;
#pragma unroll
    for (int mi = 0; mi < 2; ++mi) {
#pragma unroll
        for (int nj = 0; nj < 2; ++nj) {
            const int c = c0 + n0w + 8 * nj + 2 * q;
            const int m = 16 * mi + g;
            unsigned* p0 = g_bap + (size_t)b * KTOT + (size_t)m * CC + c;
            p0[0] = f2tf(d[mi][nj][0] * inv);
            p0[1] = f2tf(d[mi][nj][1] * inv);
            unsigned* p1 = g_bap + (size_t)b * KTOT + (size_t)(m + 8) * CC + c;
            p1[0] = f2tf(d[mi][nj][2] * inv);
            p1[1] = f2tf(d[mi][nj][3] * inv);
        }
    }
}

// ============================================================================
// Kernel 3 (tf32 + cp.async, 4-stage, KS3=64): partials bap @ Wc^T.
// grid (64, 7), block 128 (4 warps, 16n each). Issue distance 3; exact
// drain waits. KS3=64 halves g_part3 traffic vs R14 (k3 itself measured
// insensitive to KS3).
// ============================================================================
__global__ __launch_bounds__(128, 4) void k3_gemm(const float* __restrict__ Wc) {
    extern __shared__ unsigned sm3[];
    unsigned* bs  = sm3;                       // [ST3][64*SROW] tf32 bits
    unsigned* wsm = sm3 + ST3 * 64 * SROW;     // [ST3][64*SROW] fp32 bits

    const int ks = blockIdx.x;
    const int n0 = blockIdx.y * 64;
    const int t  = threadIdx.x;
    const int w    = t >> 5;
    const int lane = t & 31;
    const int g    = lane >> 2;
    const int q    = lane & 3;

    const size_t kbase = (size_t)ks * KSLICE3;

    int srow[4], sk4[4];
#pragma unroll
    for (int r = 0; r < 4; ++r) {
        const int idx = t + 128 * r;
        srow[r] = idx >> 3;
        sk4[r]  = idx & 7;
    }
    unsigned bdst[4], wdst[4];
#pragma unroll
    for (int r = 0; r < 4; ++r) {
        bdst[r] = (unsigned)__cvta_generic_to_shared(&bs[srow[r] * SROW + 4 * sk4[r]]);
        wdst[r] = (unsigned)__cvta_generic_to_shared(&wsm[srow[r] * SROW + 4 * sk4[r]]);
    }
    const unsigned stage_bytes = 64 * SROW * 4;

    float d[4][2][4];
#pragma unroll
    for (int i = 0; i < 4; ++i)
#pragma unroll
        for (int j = 0; j < 2; ++j)
#pragma unroll
            for (int r = 0; r < 4; ++r) d[i][j][r] = 0.0f;

    auto issue = [&](int ch) {
        const int st = ch % ST3;
        const size_t kb = kbase + (size_t)ch * KCH;
#pragma unroll
        for (int r = 0; r < 4; ++r) {
            cp16(bdst[r] + st * stage_bytes,
                 g_bap + (size_t)srow[r] * KTOT + kb + 4 * sk4[r]);
            const int n = n0 + srow[r];
            const float* src = (n < NC)
                ? Wc + (size_t)n * KTOT + kb + 4 * sk4[r] : Wc;
            cp16z(wdst[r] + st * stage_bytes, src, (n < NC) ? 16 : 0);
        }
        cp_commit();
    };

    issue(0);
    issue(1);
    issue(2);

    for (int ch = 0; ch < NCH; ++ch) {
        if (ch + 3 < NCH) {
            issue(ch + 3);
            asm volatile("cp.async.wait_group 3;");
        } else if (ch + 2 < NCH) {
            asm volatile("cp.async.wait_group 2;");
        } else if (ch + 1 < NCH) {
            asm volatile("cp.async.wait_group 1;");
        } else {
            asm volatile("cp.async.wait_group 0;");
        }
        __syncthreads();

        const int st = ch % ST3;
        const unsigned* bsb = bs  + st * (64 * SROW);
        const unsigned* wsb = wsm + st * (64 * SROW);
#pragma unroll
        for (int s = 0; s < 4; ++s) {
            const int k0 = 8 * s;
            unsigned b0[2], b1[2];
#pragma unroll
            for (int j = 0; j < 2; ++j) {
                const int n = 16 * w + 8 * j + g;
                b0[j] = u2tf(wsb[n * SROW + k0 + q]);
                b1[j] = u2tf(wsb[n * SROW + k0 + q + 4]);
            }
#pragma unroll
            for (int i = 0; i < 4; ++i) {
                const unsigned a0 = bsb[(16 * i + g)     * SROW + k0 + q];
                const unsigned a1 = bsb[(16 * i + 8 + g) * SROW + k0 + q];
                const unsigned a2 = bsb[(16 * i + g)     * SROW + k0 + q + 4];
                const unsigned a3 = bsb[(16 * i + 8 + g) * SROW + k0 + q + 4];
#pragma unroll
                for (int j = 0; j < 2; ++j)
                    mma_tf32(d[i][j], a0, a1, a2, a3, b0[j], b1[j]);
            }
        }
        __syncthreads();
    }

#pragma unroll
    for (int i = 0; i < 4; ++i) {
#pragma unroll
        for (int j = 0; j < 2; ++j) {
            const int n = n0 + 16 * w + 8 * j + 2 * q;
            if (n < NC) {
                const int m0 = 16 * i + g;
                float* p0 = g_part3 + ((size_t)ks * BB + m0) * NC + n;
                p0[0] = d[i][j][0];
                p0[1] = d[i][j][1];
                float* p1 = g_part3 + ((size_t)ks * BB + m0 + 8) * NC + n;
                p1[0] = d[i][j][2];
                p1[1] = d[i][j][3];
            }
        }
    }
}

// ============================================================================
// Kernel 3b: reduce K-split partials + bias -> out [64][396].
// ============================================================================
__global__ __launch_bounds__(256) void k3_reduce(const float* __restrict__ bc,
                                                 float* __restrict__ out) {
    const int i = blockIdx.x * 256 + threadIdx.x;
    const int n = i % NC;
    float s = bc[n];
#pragma unroll 16
    for (int j = 0; j < KS3; ++j)
        s += g_part3[(size_t)j * (BB * NC) + i];
    out[i] = s;
}

// ============================================================================
extern "C" void kernel_launch(void* const* d_in, const int* in_sizes, int n_in,
                              void* d_out, int out_size) {
    const float* x  = (const float*)d_in[0];
    const float* Wa = (const float*)d_in[1];
    const float* ba = (const float*)d_in[2];
    const float* Wc = (const float*)d_in[3];
    const float* bc = (const float*)d_in[4];
    float* out = (float*)d_out;

    const int smem_k1 = (2 * 32 * XST + 2 * 32 * WST) * 4;   // 44032 B
    const int smem_k2 = (32 + 64) * K2ST * 4;                // 76800 B
    const int smem_k3 = 2 * ST3 * 64 * SROW * 4;             // 73728 B
    cudaFuncSetAttribute(k1_logits, cudaFuncAttributeMaxDynamicSharedMemorySize, smem_k1);
    cudaFuncSetAttribute(k2_bap,    cudaFuncAttributeMaxDynamicSharedMemorySize, smem_k2);
    cudaFuncSetAttribute(k3_gemm,   cudaFuncAttributeMaxDynamicSharedMemorySize, smem_k3);

    k1_logits<<<dim3(BB, KS1, NS1), 256, smem_k1>>>(x, Wa);
    k1b_sigmoid<<<(BB * MM * HW) / 256, 256>>>(ba);
    k2_bap<<<dim3(CC / 64, BB), 128, smem_k2>>>(x);
    k3_gemm<<<dim3(KS3, NT3), 128, smem_k3>>>(Wc);
    k3_reduce<<<(BB * NC) / 256, 256>>>(bc, out);

    (void)in_sizes; (void)n_in; (void)out_size;
}

// round 17
// speedup vs baseline: 1.0535x; 1.0532x over previous
#include <cuda_runtime.h>
#include <cuda_bf16.h>
#include <math.h>

// Problem constants
#define BB   64
#define CC   2048
#define HW   196
#define MM   32
#define NC   396
#define KTOT (MM * CC)          // 65536

// kernel-1 (tf32 tensor) split-K — R13 config (measured best)
#define KS1   4
#define KSL1  (CC / KS1)        // 512
#define XST   232               // xs row stride (words); 232%32=8 -> conflict-free
#define WST   36                // Wa row stride

// kernel-2 (tf32 + cp.async staging) — frozen R13
#define K2ST  200               // smem row stride; 200%32=8

// kernel-3: tf32 + cp.async, 4-stage pipeline, 128 thr, KS3=128 (R14 best)
#define KS3       128
#define KSLICE3   (KTOT / KS3)  // 512
#define KCH       32
#define NCH       (KSLICE3 / KCH)  // 16
#define NT3       7
#define SROW      36
#define ST3       4             // pipeline stages

// -------- scratch (device globals; no runtime allocation) --------
__device__ float    g_part1[KS1 * BB * MM * HW];  // [ks][b][m][hw]
__device__ float    g_A    [BB * MM * HW];        // [b][m][hw]
__device__ unsigned g_bap  [BB * KTOT];           // tf32 bits, [b][m*2048+c]
__device__ float    g_part3[KS3 * BB * NC];       // [ks][b][n] 13 MB

// -------- tf32 helpers (validated R7/R8) --------
__device__ __forceinline__ unsigned f2tf(float f) {
    unsigned r;
    asm("cvt.rna.tf32.f32 %0, %1;" : "=r"(r) : "f"(f));
    return r;
}
__device__ __forceinline__ unsigned u2tf(unsigned u) {
    return f2tf(__uint_as_float(u));
}
__device__ __forceinline__ void mma_tf32(float* d,
                                         unsigned a0, unsigned a1,
                                         unsigned a2, unsigned a3,
                                         unsigned b0, unsigned b1) {
    asm("mma.sync.aligned.m16n8k8.row.col.f32.tf32.tf32.f32 "
        "{%0,%1,%2,%3}, {%4,%5,%6,%7}, {%8,%9}, {%0,%1,%2,%3};"
        : "+f"(d[0]), "+f"(d[1]), "+f"(d[2]), "+f"(d[3])
        : "r"(a0), "r"(a1), "r"(a2), "r"(a3), "r"(b0), "r"(b1));
}
// -------- cp.async helpers --------
__device__ __forceinline__ void cp16(unsigned dst_smem, const void* src) {
    asm volatile("cp.async.cg.shared.global [%0], [%1], 16;"
                 :: "r"(dst_smem), "l"(src));
}
__device__ __forceinline__ void cp16z(unsigned dst_smem, const void* src, int srcbytes) {
    asm volatile("cp.async.cg.shared.global [%0], [%1], 16, %2;"
                 :: "r"(dst_smem), "l"(src), "r"(srcbytes));
}
__device__ __forceinline__ void cp_commit() {
    asm volatile("cp.async.commit_group;");
}

// ============================================================================
// Kernel 1 (tf32, R13 exact — measured 45us): partial logits.
// grid (64 b, 4 ks), block 256 (8 warps: 2m x 4n, warp tile 16m x 56n).
// Double-buffered, register-prefetched.
// ============================================================================
__global__ __launch_bounds__(256) void k1_logits(const float* __restrict__ x,
                                                 const float* __restrict__ Wa) {
    extern __shared__ unsigned sm1[];
    unsigned* xs  = sm1;                 // [2][32*232]
    unsigned* was = sm1 + 2 * 32 * XST;  // [2][32*36]

    const int b  = blockIdx.x;
    const int ks = blockIdx.y;
    const int t  = threadIdx.x;
    const int w    = t >> 5;
    const int lane = t & 31;
    const int g    = lane >> 2;
    const int q    = lane & 3;
    const int m0   = (w & 1) * 16;
    const int n0w  = (w >> 1) * 56;

    for (int i = t; i < 2 * 32 * 36; i += 256) {
        const int buf = i / 1152;
        const int r   = (i % 1152) / 36;
        const int c   = (i % 1152) % 36;
        xs[buf * (32 * XST) + r * XST + 196 + c] = 0;
    }

    float d[7][4];
#pragma unroll
    for (int j = 0; j < 7; ++j)
#pragma unroll
        for (int r = 0; r < 4; ++r) d[j][r] = 0.0f;

    const float* xb = x + (size_t)b * CC * HW;
    const int c_base = ks * KSL1;

    const int wrow = t >> 3, wcol4 = t & 7;

    float4 xv[7], wv;
#pragma unroll
    for (int r = 0; r < 7; ++r) {
        const int idx = t + 256 * r;
        if (idx < 1568) {
            const int row = idx / 49, col4 = idx % 49;
            xv[r] = *(const float4*)(xb + (size_t)(c_base + row) * HW + 4 * col4);
        }
    }
    wv = *(const float4*)(Wa + (size_t)wrow * CC + c_base + 4 * wcol4);

    for (int ch = 0; ch < KSL1 / 32; ++ch) {
        const int buf = ch & 1;
        unsigned* xsb = xs  + buf * (32 * XST);
        unsigned* wsb = was + buf * (32 * WST);
#pragma unroll
        for (int r = 0; r < 7; ++r) {
            const int idx = t + 256 * r;
            if (idx < 1568) {
                const int row = idx / 49, col4 = idx % 49;
                unsigned* dst = &xsb[row * XST + 4 * col4];
                dst[0] = f2tf(xv[r].x); dst[1] = f2tf(xv[r].y);
                dst[2] = f2tf(xv[r].z); dst[3] = f2tf(xv[r].w);
            }
        }
        {
            unsigned* dst = &wsb[wrow * WST + 4 * wcol4];
            dst[0] = f2tf(wv.x); dst[1] = f2tf(wv.y);
            dst[2] = f2tf(wv.z); dst[3] = f2tf(wv.w);
        }
        __syncthreads();

        if (ch + 1 < KSL1 / 32) {
            const int cb = c_base + (ch + 1) * 32;
#pragma unroll
            for (int r = 0; r < 7; ++r) {
                const int idx = t + 256 * r;
                if (idx < 1568) {
                    const int row = idx / 49, col4 = idx % 49;
                    xv[r] = *(const float4*)(xb + (size_t)(cb + row) * HW + 4 * col4);
                }
            }
            wv = *(const float4*)(Wa + (size_t)wrow * CC + cb + 4 * wcol4);
        }

#pragma unroll
        for (int s = 0; s < 4; ++s) {
            const int k0 = 8 * s;
            const unsigned a0 = wsb[(m0 + g)     * WST + k0 + q];
            const unsigned a1 = wsb[(m0 + 8 + g) * WST + k0 + q];
            const unsigned a2 = wsb[(m0 + g)     * WST + k0 + q + 4];
            const unsigned a3 = wsb[(m0 + 8 + g) * WST + k0 + q + 4];
#pragma unroll
            for (int j = 0; j < 7; ++j) {
                const int n = n0w + 8 * j + g;
                const unsigned b0 = xsb[(k0 + q)     * XST + n];
                const unsigned b1 = xsb[(k0 + q + 4) * XST + n];
                mma_tf32(d[j], a0, a1, a2, a3, b0, b1);
            }
        }
        __syncthreads();
    }

    const size_t base = ((size_t)ks * BB + b) * (MM * HW);
#pragma unroll
    for (int j = 0; j < 7; ++j) {
        const int n = n0w + 8 * j + 2 * q;
        if (n < HW) {
            float* p0 = g_part1 + base + (size_t)(m0 + g) * HW + n;
            p0[0] = d[j][0]; p0[1] = d[j][1];
            float* p1 = g_part1 + base + (size_t)(m0 + 8 + g) * HW + n;
            p1[0] = d[j][2]; p1[1] = d[j][3];
        }
    }
}

// ============================================================================
// Kernel 1b: reduce split-K partials, add bias, sigmoid -> g_A.
// ============================================================================
__global__ __launch_bounds__(256) void k1b_sigmoid(const float* __restrict__ ba) {
    const int i = blockIdx.x * 256 + threadIdx.x;
    const int m = (i / HW) & (MM - 1);
    float z = ba[m];
#pragma unroll
    for (int s = 0; s < KS1; ++s)
        z += g_part1[(size_t)s * (BB * MM * HW) + i];
    g_A[i] = 1.0f / (1.0f + expf(-z));
}

// ============================================================================
// Kernel 2 (tf32 + cp.async staging, frozen R13 — measured ~20us):
// bap -> tf32 bits in g_bap.
// ============================================================================
__global__ __launch_bounds__(128) void k2_bap(const float* __restrict__ x) {
    extern __shared__ unsigned sm2u[];
    unsigned* as = sm2u;             // [32][200] fp32 bits
    unsigned* xs = sm2u + 32 * K2ST; // [64][200] fp32 bits

    const int b  = blockIdx.y;
    const int c0 = blockIdx.x * 64;
    const int t  = threadIdx.x;
    const int w    = t >> 5;
    const int lane = t & 31;
    const int g    = lane >> 2;
    const int q    = lane & 3;
    const int n0w  = w * 16;

    const unsigned abase = (unsigned)__cvta_generic_to_shared(as);
    const unsigned xbase = (unsigned)__cvta_generic_to_shared(xs);

    {
        const float* asrc = g_A + (size_t)b * (MM * HW);
        for (int i = t; i < 32 * 49; i += 128) {
            const int row = i / 49, col4 = i % 49;
            cp16(abase + (row * K2ST + 4 * col4) * 4,
                 asrc + (size_t)row * HW + 4 * col4);
        }
        const float* xsrc = x + ((size_t)b * CC + c0) * HW;
        for (int i = t; i < 64 * 49; i += 128) {
            const int row = i / 49, col4 = i % 49;
            cp16(xbase + (row * K2ST + 4 * col4) * 4,
                 xsrc + (size_t)row * HW + 4 * col4);
        }
        cp_commit();
    }
    if (t < 32 * 4) as[(t >> 2) * K2ST + 196 + (t & 3)] = 0;
    for (int i = t; i < 64 * 4; i += 128)
        xs[(i >> 2) * K2ST + 196 + (i & 3)] = 0;

    asm volatile("cp.async.wait_group 0;");
    __syncthreads();

    float d[2][2][4];
#pragma unroll
    for (int mi = 0; mi < 2; ++mi)
#pragma unroll
        for (int nj = 0; nj < 2; ++nj)
#pragma unroll
            for (int r = 0; r < 4; ++r) d[mi][nj][r] = 0.0f;

#pragma unroll
    for (int s = 0; s < 25; ++s) {
        const int k0 = 8 * s;
        unsigned b0[2], b1[2];
#pragma unroll
        for (int nj = 0; nj < 2; ++nj) {
            const int n = n0w + 8 * nj + g;
            b0[nj] = u2tf(xs[n * K2ST + k0 + q]);
            b1[nj] = u2tf(xs[n * K2ST + k0 + q + 4]);
        }
#pragma unroll
        for (int mi = 0; mi < 2; ++mi) {
            const unsigned a0 = u2tf(as[(16 * mi + g)     * K2ST + k0 + q]);
            const unsigned a1 = u2tf(as[(16 * mi + 8 + g) * K2ST + k0 + q]);
            const unsigned a2 = u2tf(as[(16 * mi + g)     * K2ST + k0 + q + 4]);
            const unsigned a3 = u2tf(as[(16 * mi + 8 + g) * K2ST + k0 + q + 4]);
#pragma unroll
            for (int nj = 0; nj < 2; ++nj)
                mma_tf32(d[mi][nj], a0, a1, a2, a3, b0[nj], b1[nj]);
        }
    }

    const float inv = 1.0f / 196.0f;
#pragma unroll
    for (int mi = 0; mi < 2; ++mi) {
#pragma unroll
        for (int nj = 0; nj < 2; ++nj) {
            const int c = c0 + n0w + 8 * nj + 2 * q;
            const int m = 16 * mi + g;
            unsigned* p0 = g_bap + (size_t)b * KTOT + (size_t)m * CC + c;
            p0[0] = f2tf(d[mi][nj][0] * inv);
            p0[1] = f2tf(d[mi][nj][1] * inv);
            unsigned* p1 = g_bap + (size_t)b * KTOT + (size_t)(m + 8) * CC + c;
            p1[0] = f2tf(d[mi][nj][2] * inv);
            p1[1] = f2tf(d[mi][nj][3] * inv);
        }
    }
}

// ============================================================================
// Kernel 3 (tf32 + cp.async, 4-stage, KS3=128 — R14's k3, measured 38.8us):
// partials bap @ Wc^T. grid (128, 7), block 128 (4 warps, 16n each).
// Issue distance 3; exact drain waits. Wc bounds check hoisted to a
// block-uniform flag (full for blockIdx.y < 6).
// ============================================================================
__global__ __launch_bounds__(128, 4) void k3_gemm(const float* __restrict__ Wc) {
    extern __shared__ unsigned sm3[];
    unsigned* bs  = sm3;                       // [ST3][64*SROW] tf32 bits
    unsigned* wsm = sm3 + ST3 * 64 * SROW;     // [ST3][64*SROW] fp32 bits

    const int ks = blockIdx.x;
    const int n0 = blockIdx.y * 64;
    const bool full = (n0 + 64 <= NC);
    const int t  = threadIdx.x;
    const int w    = t >> 5;
    const int lane = t & 31;
    const int g    = lane >> 2;
    const int q    = lane & 3;

    const size_t kbase = (size_t)ks * KSLICE3;

    int srow[4], sk4[4];
#pragma unroll
    for (int r = 0; r < 4; ++r) {
        const int idx = t + 128 * r;
        srow[r] = idx >> 3;
        sk4[r]  = idx & 7;
    }
    unsigned bdst[4], wdst[4];
#pragma unroll
    for (int r = 0; r < 4; ++r) {
        bdst[r] = (unsigned)__cvta_generic_to_shared(&bs[srow[r] * SROW + 4 * sk4[r]]);
        wdst[r] = (unsigned)__cvta_generic_to_shared(&wsm[srow[r] * SROW + 4 * sk4[r]]);
    }
    const unsigned stage_bytes = 64 * SROW * 4;

    float d[4][2][4];
#pragma unroll
    for (int i = 0; i < 4; ++i)
#pragma unroll
        for (int j = 0; j < 2; ++j)
#pragma unroll
            for (int r = 0; r < 4; ++r) d[i][j][r] = 0.0f;

    auto issue = [&](int ch) {
        const int st = ch % ST3;
        const size_t kb = kbase + (size_t)ch * KCH;
        if (full) {
#pragma unroll
            for (int r = 0; r < 4; ++r) {
                cp16(bdst[r] + st * stage_bytes,
                     g_bap + (size_t)srow[r] * KTOT + kb + 4 * sk4[r]);
                cp16(wdst[r] + st * stage_bytes,
                     Wc + (size_t)(n0 + srow[r]) * KTOT + kb + 4 * sk4[r]);
            }
        } else {
#pragma unroll
            for (int r = 0; r < 4; ++r) {
                cp16(bdst[r] + st * stage_bytes,
                     g_bap + (size_t)srow[r] * KTOT + kb + 4 * sk4[r]);
                const int n = n0 + srow[r];
                const float* src = (n < NC)
                    ? Wc + (size_t)n * KTOT + kb + 4 * sk4[r] : Wc;
                cp16z(wdst[r] + st * stage_bytes, src, (n < NC) ? 16 : 0);
            }
        }
        cp_commit();
    };

    issue(0);
    issue(1);
    issue(2);

    for (int ch = 0; ch < NCH; ++ch) {
        if (ch + 3 < NCH) {
            issue(ch + 3);
            asm volatile("cp.async.wait_group 3;");
        } else if (ch + 2 < NCH) {
            asm volatile("cp.async.wait_group 2;");
        } else if (ch + 1 < NCH) {
            asm volatile("cp.async.wait_group 1;");
        } else {
            asm volatile("cp.async.wait_group 0;");
        }
        __syncthreads();

        const int st = ch % ST3;
        const unsigned* bsb = bs  + st * (64 * SROW);
        const unsigned* wsb = wsm + st * (64 * SROW);
#pragma unroll
        for (int s = 0; s < 4; ++s) {
            const int k0 = 8 * s;
            unsigned b0[2], b1[2];
#pragma unroll
            for (int j = 0; j < 2; ++j) {
                const int n = 16 * w + 8 * j + g;
                b0[j] = u2tf(wsb[n * SROW + k0 + q]);
                b1[j] = u2tf(wsb[n * SROW + k0 + q + 4]);
            }
#pragma unroll
            for (int i = 0; i < 4; ++i) {
                const unsigned a0 = bsb[(16 * i + g)     * SROW + k0 + q];
                const unsigned a1 = bsb[(16 * i + 8 + g) * SROW + k0 + q];
                const unsigned a2 = bsb[(16 * i + g)     * SROW + k0 + q + 4];
                const unsigned a3 = bsb[(16 * i + 8 + g) * SROW + k0 + q + 4];
#pragma unroll
                for (int j = 0; j < 2; ++j)
                    mma_tf32(d[i][j], a0, a1, a2, a3, b0[j], b1[j]);
            }
        }
        __syncthreads();
    }

#pragma unroll
    for (int i = 0; i < 4; ++i) {
#pragma unroll
        for (int j = 0; j < 2; ++j) {
            const int n = n0 + 16 * w + 8 * j + 2 * q;
            if (n < NC) {
                const int m0 = 16 * i + g;
                float* p0 = g_part3 + ((size_t)ks * BB + m0) * NC + n;
                p0[0] = d[i][j][0];
                p0[1] = d[i][j][1];
                float* p1 = g_part3 + ((size_t)ks * BB + m0 + 8) * NC + n;
                p1[0] = d[i][j][2];
                p1[1] = d[i][j][3];
            }
        }
    }
}

// ============================================================================
// Kernel 3b: reduce K-split partials + bias -> out [64][396].
// ============================================================================
__global__ __launch_bounds__(256) void k3_reduce(const float* __restrict__ bc,
                                                 float* __restrict__ out) {
    const int i = blockIdx.x * 256 + threadIdx.x;
    const int n = i % NC;
    float s = bc[n];
#pragma unroll 16
    for (int j = 0; j < KS3; ++j)
        s += g_part3[(size_t)j * (BB * NC) + i];
    out[i] = s;
}

// ============================================================================
extern "C" void kernel_launch(void* const* d_in, const int* in_sizes, int n_in,
                              void* d_out, int out_size) {
    const float* x  = (const float*)d_in[0];
    const float* Wa = (const float*)d_in[1];
    const float* ba = (const float*)d_in[2];
    const float* Wc = (const float*)d_in[3];
    const float* bc = (const float*)d_in[4];
    float* out = (float*)d_out;

    const int smem_k1 = (2 * 32 * XST + 2 * 32 * WST) * 4;   // 68608 B
    const int smem_k2 = (32 + 64) * K2ST * 4;                // 76800 B
    const int smem_k3 = 2 * ST3 * 64 * SROW * 4;             // 73728 B
    cudaFuncSetAttribute(k1_logits, cudaFuncAttributeMaxDynamicSharedMemorySize, smem_k1);
    cudaFuncSetAttribute(k2_bap,    cudaFuncAttributeMaxDynamicSharedMemorySize, smem_k2);
    cudaFuncSetAttribute(k3_gemm,   cudaFuncAttributeMaxDynamicSharedMemorySize, smem_k3);

    k1_logits<<<dim3(BB, KS1), 256, smem_k1>>>(x, Wa);
    k1b_sigmoid<<<(BB * MM * HW) / 256, 256>>>(ba);
    k2_bap<<<dim3(CC / 64, BB), 128, smem_k2>>>(x);
    k3_gemm<<<dim3(KS3, NT3), 128, smem_k3>>>(Wc);
    k3_reduce<<<(BB * NC) / 256, 256>>>(bc, out);

    (void)in_sizes; (void)n_in; (void)out_size;
}